// round 15
// baseline (speedup 1.0000x reference)
#include <cuda_runtime.h>
#include <cuda_fp16.h>
#include <math.h>
#include <stdint.h>

#define N_NODES 100000
#define N_EDGES 1600000
#define FNODE   64
#define FEDGE   32
#define EPSBN   1e-5f

// ---------------- device scratch --------------------------------------------
__device__ __align__(16) __half g_Ph[(size_t)N_NODES * 128];  // node @ W[0:64,:]   fp16
__device__ __align__(16) __half g_Qh[(size_t)N_NODES * 128];  // node @ W[64:128,:] fp16
__device__ __align__(16) __half g_Eh[(size_t)N_EDGES * 128];  // ef @ Wc + bias, fp16
__device__ __align__(16) __half g_Yh[(size_t)N_EDGES * 128];  // pre-BN edge outputs, fp16
__device__ __align__(16) float  g_agg[(size_t)N_NODES * FNODE];
__device__ double g_sum[128];
__device__ double g_sumsq[128];
__device__ __align__(16) float  g_escale[128];
__device__ __align__(16) float  g_eshift[128];
__device__ double g_nsum[FNODE];
__device__ double g_nsumsq[FNODE];

// ---------------- helpers ----------------------------------------------------
__device__ __forceinline__ unsigned long long pk2(float x, float y) {
    unsigned long long r;
    asm("mov.b64 %0, {%1, %2};" : "=l"(r) : "f"(x), "f"(y));
    return r;
}
__device__ __forceinline__ void upk2(unsigned long long v, float& x, float& y) {
    asm("mov.b64 {%0, %1}, %2;" : "=f"(x), "=f"(y) : "l"(v));
}
__device__ __forceinline__ void fma2(unsigned long long& acc,
                                     unsigned long long a, unsigned long long b) {
    asm("fma.rn.f32x2 %0, %1, %2, %0;" : "+l"(acc) : "l"(a), "l"(b));
}
__device__ __forceinline__ float tanhfast(float x) {
    float r;
    asm("tanh.approx.f32 %0, %1;" : "=f"(r) : "f"(x));
    return r;
}
__device__ __forceinline__ float sigf(float x) {
    return fmaf(0.5f, tanhfast(0.5f * x), 0.5f);
}
__device__ __forceinline__ float spf(float x) {
    return fmaxf(x, 0.0f) + __logf(1.0f + __expf(-fabsf(x)));
}
__device__ __forceinline__ void red_add_v4(float* p, float4 v) {
    asm volatile("red.global.add.v4.f32 [%0], {%1, %2, %3, %4};"
                 :: "l"(p), "f"(v.x), "f"(v.y), "f"(v.z), "f"(v.w) : "memory");
}
__device__ __forceinline__ unsigned f2tf32(float f) {
    unsigned r;
    asm("cvt.rna.tf32.f32 %0, %1;" : "=r"(r) : "f"(f));
    return r;
}
__device__ __forceinline__ void mma_tf32(float& c0, float& c1, float& c2, float& c3,
                                         unsigned a0, unsigned a1, unsigned a2, unsigned a3,
                                         unsigned b0, unsigned b1) {
    asm("mma.sync.aligned.m16n8k8.row.col.f32.tf32.tf32.f32 "
        "{%0,%1,%2,%3}, {%4,%5,%6,%7}, {%8,%9}, {%0,%1,%2,%3};"
        : "+f"(c0), "+f"(c1), "+f"(c2), "+f"(c3)
        : "r"(a0), "r"(a1), "r"(a2), "r"(a3), "r"(b0), "r"(b1));
}

#define NT  5                      // node tiles per k1 block; grid = 625
#define APAD 36
#define WPAD 136
#define EPAD 136                   // sE pitch in halfs
#define EPW2 8                     // edges per warp in kA_gather

// ---------------- K1: P/Q node GEMMs, 5 tiles/block + scratch zeroing ---------
__global__ void __launch_bounds__(256)
k1_node_gemm(const float* __restrict__ node,
             const float* __restrict__ Wint,
             const float* __restrict__ Wupd) {
    __shared__ __align__(16) float sn[32 * 64];
    __shared__ __align__(16) float sw[64 * 128];
    const int tid = threadIdx.x;
    const int nbase0 = blockIdx.x * (32 * NT);

    {
        float4* aggv = (float4*)g_agg;
        const int per = (N_NODES * FNODE / 4) / 625;  // 2560
        const int base = blockIdx.x * per;
        for (int j = tid; j < per; j += 256)
            aggv[base + j] = make_float4(0.f, 0.f, 0.f, 0.f);
        if (blockIdx.x == 0 && tid < 128) {
            g_sum[tid] = 0.0;
            g_sumsq[tid] = 0.0;
            if (tid < 64) { g_nsum[tid] = 0.0; g_nsumsq[tid] = 0.0; }
        }
    }

    const int cg = tid & 31;
    const int ng = tid >> 5;

    for (int pass = 0; pass < 2; ++pass) {
        __syncthreads();
        for (int i = tid; i < 64 * 128; i += 256) {
            int k = i >> 7, c = i & 127;
            int krow = pass * 64 + k;
            sw[i] = (c < 64) ? Wint[krow * 64 + c] : Wupd[krow * 64 + (c - 64)];
        }

        for (int t = 0; t < NT; ++t) {
            __syncthreads();
            const int nbase = nbase0 + t * 32;
            for (int i = tid; i < 32 * 64; i += 256)
                sn[i] = node[(size_t)nbase * 64 + i];
            __syncthreads();

            unsigned long long a0[4], a1[4];
#pragma unroll
            for (int i = 0; i < 4; ++i) { a0[i] = 0ull; a1[i] = 0ull; }

#pragma unroll 8
            for (int k = 0; k < 64; ++k) {
                const ulonglong2 w = *(const ulonglong2*)&sw[k * 128 + 4 * cg];
#pragma unroll
                for (int i = 0; i < 4; ++i) {
                    const float nv = sn[(4 * ng + i) * 64 + k];
                    const unsigned long long n2 = pk2(nv, nv);
                    fma2(a0[i], n2, w.x);
                    fma2(a1[i], n2, w.y);
                }
            }
            __half* dstp = (pass == 0) ? g_Ph : g_Qh;
#pragma unroll
            for (int i = 0; i < 4; ++i) {
                float x, y, z, w2;
                upk2(a0[i], x, y);
                upk2(a1[i], z, w2);
                const __half2 h01 = __floats2half2_rn(x, y);
                const __half2 h23 = __floats2half2_rn(z, w2);
                const uint2 hv = make_uint2(*(const unsigned*)&h01, *(const unsigned*)&h23);
                *(uint2*)&dstp[(size_t)(nbase + 4 * ng + i) * 128 + 4 * cg] = hv;
            }
        }
    }
}

// ---------------- KE: dense tf32 mma GEMM  Eh = ef @ Wc + b  -------------------
// Block = 128 edges. stage -> mma -> smem transpose (fp16, +bias) -> coalesced store.
__global__ void __launch_bounds__(256)
kE_gemm(const float* __restrict__ ef,
        const float* __restrict__ Wint,
        const float* __restrict__ Wupd,
        const float* __restrict__ bint,
        const float* __restrict__ bupd) {
    __shared__ __align__(16) char arena[128 * APAD * 4 + 32 * WPAD * 4];  // 35840 B
    __shared__ __align__(16) float sb[128];
    unsigned* sA = (unsigned*)arena;                       // 128 x APAD
    unsigned* sW = (unsigned*)(arena + 128 * APAD * 4);    // 32 x WPAD
    __half*   sE = (__half*)arena;                         // 128 x EPAD (aliases, post-mma)

    const int tid = threadIdx.x;
    const size_t ebase = (size_t)blockIdx.x * 128;

    // stage ef -> tf32
    {
        const float4* efv = (const float4*)(ef + ebase * 32);
#pragma unroll
        for (int it = 0; it < 4; ++it) {
            const int i = tid + it * 256;
            const float4 v = __ldcs(&efv[i]);
            const int row = i >> 3, col = (i & 7) * 4;
            unsigned* p = &sA[row * APAD + col];
            p[0] = f2tf32(v.x); p[1] = f2tf32(v.y);
            p[2] = f2tf32(v.z); p[3] = f2tf32(v.w);
        }
    }
    // stage Wc rows 128..159 -> tf32, bias
    for (int i = tid; i < 32 * 128; i += 256) {
        const int k = i >> 7, c = i & 127;
        const float w = (c < 64) ? Wint[(128 + k) * 64 + c] : Wupd[(128 + k) * 64 + (c - 64)];
        sW[k * WPAD + c] = f2tf32(w);
    }
    if (tid < 128) sb[tid] = (tid < 64) ? bint[tid] : bupd[tid - 64];
    __syncthreads();

    // mma
    const int warp = tid >> 5, lane = tid & 31;
    const int g = lane >> 2, tig = lane & 3;
    const int row0 = warp * 16 + g, row1 = row0 + 8;

    float c0[16], c1[16], c2[16], c3[16];
#pragma unroll
    for (int nt = 0; nt < 16; ++nt) { c0[nt] = 0.f; c1[nt] = 0.f; c2[nt] = 0.f; c3[nt] = 0.f; }

#pragma unroll
    for (int kt = 0; kt < 4; ++kt) {
        const unsigned a0 = sA[row0 * APAD + kt * 8 + tig];
        const unsigned a1 = sA[row1 * APAD + kt * 8 + tig];
        const unsigned a2 = sA[row0 * APAD + kt * 8 + tig + 4];
        const unsigned a3 = sA[row1 * APAD + kt * 8 + tig + 4];
#pragma unroll
        for (int nt = 0; nt < 16; ++nt) {
            const unsigned b0 = sW[(kt * 8 + tig) * WPAD + nt * 8 + g];
            const unsigned b1 = sW[(kt * 8 + tig + 4) * WPAD + nt * 8 + g];
            mma_tf32(c0[nt], c1[nt], c2[nt], c3[nt], a0, a1, a2, a3, b0, b1);
        }
    }
    __syncthreads();   // all sA/sW reads done before sE overwrites arena

    // fragments -> sE (fp16, +bias)
#pragma unroll
    for (int nt = 0; nt < 16; ++nt) {
        const int cc = nt * 8 + 2 * tig;
        const float2 bb = *(const float2*)&sb[cc];
        const __half2 h0 = __floats2half2_rn(c0[nt] + bb.x, c1[nt] + bb.y);
        const __half2 h1 = __floats2half2_rn(c2[nt] + bb.x, c3[nt] + bb.y);
        *(__half2*)&sE[row0 * EPAD + cc] = h0;
        *(__half2*)&sE[row1 * EPAD + cc] = h1;
    }
    __syncthreads();

    // coalesced store: 128 rows x 16 uint4
#pragma unroll
    for (int j = 0; j < 8; ++j) {
        const int idx = tid + j * 256;          // 0..2047
        const int row = idx >> 4, seg = idx & 15;
        const uint4 v = *(const uint4*)&sE[row * EPAD + seg * 8];
        __stcs((uint4*)&g_Eh[(ebase + row) * 128 + seg * 8], v);
    }
}

// ---------------- KA: gather P+Q+E, fp16 spill + stats (pure streaming) -------
__global__ void __launch_bounds__(256)
kA_gather(const int* __restrict__ src,
          const int* __restrict__ dst) {
    __shared__ __align__(16) float sred[8][128];
    __shared__ __align__(16) float sred2[8][128];

    const int tid = threadIdx.x;
    const int warp = tid >> 5, lane = tid & 31;
    const size_t ebase = (size_t)blockIdx.x * (8 * EPW2) + (size_t)warp * EPW2;

    float4 ls = make_float4(0.f, 0.f, 0.f, 0.f);
    float4 lq = make_float4(0.f, 0.f, 0.f, 0.f);

#pragma unroll
    for (int i = 0; i < EPW2; ++i) {
        const size_t e = ebase + i;
        const int sI = src[e];
        const int dI = dst[e];
        const uint2 eu = __ldcs((const uint2*)&g_Eh[e * 128 + 4 * lane]);
        const uint2 pu = __ldg((const uint2*)&g_Ph[(size_t)sI * 128 + 4 * lane]);
        const uint2 qu = __ldg((const uint2*)&g_Qh[(size_t)dI * 128 + 4 * lane]);
        const float2 e01 = __half22float2(*(const __half2*)&eu.x);
        const float2 e23 = __half22float2(*(const __half2*)&eu.y);
        const float2 p01 = __half22float2(*(const __half2*)&pu.x);
        const float2 p23 = __half22float2(*(const __half2*)&pu.y);
        const float2 q01 = __half22float2(*(const __half2*)&qu.x);
        const float2 q23 = __half22float2(*(const __half2*)&qu.y);

        const float x = e01.x + p01.x + q01.x;
        const float y = e01.y + p01.y + q01.y;
        const float z = e23.x + p23.x + q23.x;
        const float w = e23.y + p23.y + q23.y;

        const __half2 h01 = __floats2half2_rn(x, y);
        const __half2 h23 = __floats2half2_rn(z, w);
        const uint2 hv = make_uint2(*(const unsigned*)&h01, *(const unsigned*)&h23);
        __stcs((uint2*)&g_Yh[e * 128 + 4 * lane], hv);

        ls.x += x; ls.y += y; ls.z += z; ls.w += w;
        lq.x += x * x; lq.y += y * y; lq.z += z * z; lq.w += w * w;
    }
    *(float4*)&sred[warp][4 * lane]  = ls;
    *(float4*)&sred2[warp][4 * lane] = lq;
    __syncthreads();

    if (tid < 128) {
        float v = 0.f;
#pragma unroll
        for (int w = 0; w < 8; ++w) v += sred[w][tid];
        atomicAdd(&g_sum[tid], (double)v);
    } else {
        const int c = tid - 128;
        float v = 0.f;
#pragma unroll
        for (int w = 0; w < 8; ++w) v += sred2[w][c];
        atomicAdd(&g_sumsq[c], (double)v);
    }
}

// ---------------- K3: finalize edge BN ----------------------------------------
__global__ void k3_edge_bn(const float* __restrict__ gint,
                           const float* __restrict__ beint,
                           const float* __restrict__ gupd,
                           const float* __restrict__ beupd) {
    const int c = threadIdx.x;  // 128
    const double mu  = g_sum[c]   / (double)N_EDGES;
    const double var = g_sumsq[c] / (double)N_EDGES - mu * mu;
    const float gam = (c < 64) ? gint[c] : gupd[c - 64];
    const float bet = (c < 64) ? beint[c] : beupd[c - 64];
    const float sc = gam * rsqrtf((float)var + EPSBN);
    g_escale[c] = sc;
    g_eshift[c] = bet - (float)mu * sc;
}

// ---------------- KB: stream Yh, BN + act + scatter ----------------------------
__global__ void __launch_bounds__(256)
kB_apply(const int* __restrict__ dst) {
    const int tid = threadIdx.x;
    const int warp = tid >> 5, lane = tid & 31;
    const int s = lane & 15;
    const size_t e = (size_t)blockIdx.x * 16 + (size_t)warp * 2 + (lane >> 4);

    const uint2 gv = __ldcs((const uint2*)&g_Yh[e * 128 + 4 * s]);
    const uint2 uv = __ldcs((const uint2*)&g_Yh[e * 128 + 64 + 4 * s]);

    const float2 g01 = __half22float2(*(const __half2*)&gv.x);
    const float2 g23 = __half22float2(*(const __half2*)&gv.y);
    const float2 u01 = __half22float2(*(const __half2*)&uv.x);
    const float2 u23 = __half22float2(*(const __half2*)&uv.y);

    const float4 gs = *(const float4*)&g_escale[4 * s];
    const float4 gh = *(const float4*)&g_eshift[4 * s];
    const float4 us = *(const float4*)&g_escale[64 + 4 * s];
    const float4 uh = *(const float4*)&g_eshift[64 + 4 * s];

    float4 m;
    m.x = sigf(fmaf(g01.x, gs.x, gh.x)) * spf(fmaf(u01.x, us.x, uh.x));
    m.y = sigf(fmaf(g01.y, gs.y, gh.y)) * spf(fmaf(u01.y, us.y, uh.y));
    m.z = sigf(fmaf(g23.x, gs.z, gh.z)) * spf(fmaf(u23.x, us.z, uh.z));
    m.w = sigf(fmaf(g23.y, gs.w, gh.w)) * spf(fmaf(u23.y, us.w, uh.w));

    const int d = dst[e];
    red_add_v4(&g_agg[(size_t)d * 64 + 4 * s], m);
}

// ---------------- K5: node BN stats over agg (float4 loads) ---------------------
__global__ void __launch_bounds__(256)
k5_node_stats() {
    const int tid = threadIdx.x;
    const int c4 = (tid & 15) * 4;
    const int rsub = tid >> 4;
    const int r0 = blockIdx.x * 512 + rsub;
    const int end = min((blockIdx.x + 1) * 512, N_NODES);

    float4 s = make_float4(0.f, 0.f, 0.f, 0.f);
    float4 q = make_float4(0.f, 0.f, 0.f, 0.f);
    for (int r = r0; r < end; r += 16) {
        const float4 v = *(const float4*)&g_agg[(size_t)r * 64 + c4];
        s.x += v.x; s.y += v.y; s.z += v.z; s.w += v.w;
        q.x += v.x * v.x; q.y += v.y * v.y; q.z += v.z * v.z; q.w += v.w * v.w;
    }
    __shared__ __align__(16) float ss[16][64];
    __shared__ __align__(16) float sq[16][64];
    *(float4*)&ss[rsub][c4] = s;
    *(float4*)&sq[rsub][c4] = q;
    __syncthreads();
    if (tid < 64) {
        float a = 0.f, b = 0.f;
#pragma unroll
        for (int r = 0; r < 16; ++r) { a += ss[r][tid]; b += sq[r][tid]; }
        atomicAdd(&g_nsum[tid], (double)a);
        atomicAdd(&g_nsumsq[tid], (double)b);
    }
}

// ---------------- K6: final output (node BN folded in) --------------------------
__global__ void __launch_bounds__(256)
k6_out(const float* __restrict__ node,
       const float* __restrict__ gbn,
       const float* __restrict__ bebn,
       float* __restrict__ out) {
    __shared__ float snsc[64], snsh[64];
    const int tid = threadIdx.x;
    if (tid < 64) {
        const double mu  = g_nsum[tid]   / (double)N_NODES;
        const double var = g_nsumsq[tid] / (double)N_NODES - mu * mu;
        const float sc = gbn[tid] * rsqrtf((float)var + EPSBN);
        snsc[tid] = sc;
        snsh[tid] = bebn[tid] - (float)mu * sc;
    }
    __syncthreads();

    const size_t i = (size_t)blockIdx.x * 256 + tid;
    if (i >= (size_t)N_NODES * 64) return;
    const int c = (int)(i & 63);
    const float x = node[i] + g_agg[i] * snsc[c] + snsh[c];
    out[i] = fmaxf(x, 0.f) + log1pf(expf(-fabsf(x)));
}

// ---------------- launch ---------------------------------------------------------
extern "C" void kernel_launch(void* const* d_in, const int* in_sizes, int n_in,
                              void* d_out, int out_size) {
    const float* node  = (const float*)d_in[0];
    const float* edge  = (const float*)d_in[1];
    const int*   src   = (const int*)d_in[2];
    const int*   dst   = (const int*)d_in[3];
    const float* Wint  = (const float*)d_in[4];
    const float* bint  = (const float*)d_in[5];
    const float* gint  = (const float*)d_in[6];
    const float* beint = (const float*)d_in[7];
    const float* Wupd  = (const float*)d_in[8];
    const float* bupd  = (const float*)d_in[9];
    const float* gupd  = (const float*)d_in[10];
    const float* beupd = (const float*)d_in[11];
    const float* gbn   = (const float*)d_in[12];
    const float* bebn  = (const float*)d_in[13];
    float* out = (float*)d_out;

    k1_node_gemm<<<N_NODES / (32 * NT), 256>>>(node, Wint, Wupd);
    kE_gemm<<<N_EDGES / 128, 256>>>(edge, Wint, Wupd, bint, bupd);
    kA_gather<<<N_EDGES / (8 * EPW2), 256>>>(src, dst);
    k3_edge_bn<<<1, 128>>>(gint, beint, gupd, beupd);
    kB_apply<<<N_EDGES / 16, 256>>>(dst);
    k5_node_stats<<<(N_NODES + 511) / 512, 256>>>();
    k6_out<<<((size_t)N_NODES * 64 + 255) / 256, 256>>>(node, gbn, bebn, out);
}

// round 16
// speedup vs baseline: 1.4258x; 1.4258x over previous
#include <cuda_runtime.h>
#include <cuda_fp16.h>
#include <math.h>
#include <stdint.h>

#define N_NODES 100000
#define N_EDGES 1600000
#define FNODE   64
#define FEDGE   32
#define EPSBN   1e-5f
#define NSTRIPE 32

// ---------------- device scratch --------------------------------------------
__device__ __align__(16) __half g_Ph[(size_t)N_NODES * 128];  // node @ W[0:64,:]   fp16
__device__ __align__(16) __half g_Qh[(size_t)N_NODES * 128];  // node @ W[64:128,:] fp16
__device__ __align__(16) __half g_Yh[(size_t)N_EDGES * 128];  // pre-BN edge outputs, fp16
__device__ __align__(16) float  g_agg[(size_t)N_NODES * FNODE];
__device__ double g_sum32[NSTRIPE * 128];    // striped edge-stat accumulators
__device__ double g_sumsq32[NSTRIPE * 128];
__device__ __align__(16) float  g_escale[128];
__device__ __align__(16) float  g_eshift[128];
__device__ double g_nsum[FNODE];
__device__ double g_nsumsq[FNODE];

// ---------------- helpers ----------------------------------------------------
__device__ __forceinline__ unsigned long long pk2(float x, float y) {
    unsigned long long r;
    asm("mov.b64 %0, {%1, %2};" : "=l"(r) : "f"(x), "f"(y));
    return r;
}
__device__ __forceinline__ void upk2(unsigned long long v, float& x, float& y) {
    asm("mov.b64 {%0, %1}, %2;" : "=f"(x), "=f"(y) : "l"(v));
}
__device__ __forceinline__ void fma2(unsigned long long& acc,
                                     unsigned long long a, unsigned long long b) {
    asm("fma.rn.f32x2 %0, %1, %2, %0;" : "+l"(acc) : "l"(a), "l"(b));
}
__device__ __forceinline__ float tanhfast(float x) {
    float r;
    asm("tanh.approx.f32 %0, %1;" : "=f"(r) : "f"(x));
    return r;
}
__device__ __forceinline__ float sigf(float x) {
    return fmaf(0.5f, tanhfast(0.5f * x), 0.5f);
}
__device__ __forceinline__ float spf(float x) {
    return fmaxf(x, 0.0f) + __logf(1.0f + __expf(-fabsf(x)));
}
__device__ __forceinline__ void red_add_v4(float* p, float4 v) {
    asm volatile("red.global.add.v4.f32 [%0], {%1, %2, %3, %4};"
                 :: "l"(p), "f"(v.x), "f"(v.y), "f"(v.z), "f"(v.w) : "memory");
}

#define EPW 10                     // edges per warp  (8 warps * 10 = 80 edges/block)
#define EPB (8 * EPW)              // 80; N_EDGES / 80 = 20000 exact
#define NT  5                      // node tiles per k1 block; grid = 625

// ---------------- K1: P/Q node GEMMs, 5 tiles/block + scratch zeroing ---------
__global__ void __launch_bounds__(256)
k1_node_gemm(const float* __restrict__ node,
             const float* __restrict__ Wint,
             const float* __restrict__ Wupd) {
    __shared__ __align__(16) float sn[32 * 64];
    __shared__ __align__(16) float sw[64 * 128];
    const int tid = threadIdx.x;
    const int nbase0 = blockIdx.x * (32 * NT);

    // fold scratch zeroing into k1
    {
        float4* aggv = (float4*)g_agg;
        const int per = (N_NODES * FNODE / 4) / 625;  // 2560
        const int base = blockIdx.x * per;
        for (int j = tid; j < per; j += 256)
            aggv[base + j] = make_float4(0.f, 0.f, 0.f, 0.f);
        if (blockIdx.x == 0) {
            for (int j = tid; j < NSTRIPE * 128; j += 256) {
                g_sum32[j] = 0.0;
                g_sumsq32[j] = 0.0;
            }
            if (tid < 64) { g_nsum[tid] = 0.0; g_nsumsq[tid] = 0.0; }
        }
    }

    const int cg = tid & 31;
    const int ng = tid >> 5;

    for (int pass = 0; pass < 2; ++pass) {
        __syncthreads();
        for (int i = tid; i < 64 * 128; i += 256) {
            int k = i >> 7, c = i & 127;
            int krow = pass * 64 + k;
            sw[i] = (c < 64) ? Wint[krow * 64 + c] : Wupd[krow * 64 + (c - 64)];
        }

        for (int t = 0; t < NT; ++t) {
            __syncthreads();
            const int nbase = nbase0 + t * 32;
            for (int i = tid; i < 32 * 64; i += 256)
                sn[i] = node[(size_t)nbase * 64 + i];
            __syncthreads();

            unsigned long long a0[4], a1[4];
#pragma unroll
            for (int i = 0; i < 4; ++i) { a0[i] = 0ull; a1[i] = 0ull; }

#pragma unroll 8
            for (int k = 0; k < 64; ++k) {
                const ulonglong2 w = *(const ulonglong2*)&sw[k * 128 + 4 * cg];
#pragma unroll
                for (int i = 0; i < 4; ++i) {
                    const float nv = sn[(4 * ng + i) * 64 + k];
                    const unsigned long long n2 = pk2(nv, nv);
                    fma2(a0[i], n2, w.x);
                    fma2(a1[i], n2, w.y);
                }
            }
            __half* dstp = (pass == 0) ? g_Ph : g_Qh;
#pragma unroll
            for (int i = 0; i < 4; ++i) {
                float x, y, z, w2;
                upk2(a0[i], x, y);
                upk2(a1[i], z, w2);
                const __half2 h01 = __floats2half2_rn(x, y);
                const __half2 h23 = __floats2half2_rn(z, w2);
                const uint2 hv = make_uint2(*(const unsigned*)&h01, *(const unsigned*)&h23);
                *(uint2*)&dstp[(size_t)(nbase + 4 * ng + i) * 128 + 4 * cg] = hv;
            }
        }
    }
}

// ---------------- KA: edge GEMM + fp16 gather + fp16 spill + striped stats ----
__global__ void __launch_bounds__(256, 3)
kA_edge(const float* __restrict__ ef,
        const int* __restrict__ src,
        const int* __restrict__ dst,
        const float* __restrict__ Wint,
        const float* __restrict__ Wupd,
        const float* __restrict__ bint,
        const float* __restrict__ bupd) {
    __shared__ __align__(16) float swc[32 * 128];          // 16 KB weights
    __shared__ __align__(16) float sef[8 * EPW * 32];      // 10 KB staged ef (unpacked)
    __shared__ __align__(16) float sb[128];
    __shared__ __align__(16) float sred[8][128];
    __shared__ __align__(16) float sred2[8][128];

    const int tid = threadIdx.x;
    for (int i = tid; i < 32 * 128; i += 256) {
        int k = i >> 7, c = i & 127;
        swc[i] = (c < 64) ? Wint[(128 + k) * 64 + c] : Wupd[(128 + k) * 64 + (c - 64)];
    }
    if (tid < 128) sb[tid] = (tid < 64) ? bint[tid] : bupd[tid - 64];
    __syncthreads();

    const int warp = tid >> 5, lane = tid & 31;
    const size_t ebase = (size_t)blockIdx.x * EPB + (size_t)warp * EPW;
    const float4 b4 = *(const float4*)&sb[4 * lane];
    float* sefp = &sef[warp * (EPW * 32)];

#pragma unroll
    for (int i = 0; i < EPW; ++i)
        sefp[i * 32 + lane] = __ldcs(&ef[(ebase + i) * 32 + lane]);
    __syncwarp();

    unsigned long long a0[EPW], a1[EPW];
    {
        int sI[EPW], dI[EPW];
#pragma unroll
        for (int i = 0; i < EPW; ++i) {
            sI[i] = src[ebase + i];
            dI[i] = dst[ebase + i];
        }
#pragma unroll
        for (int i = 0; i < EPW; ++i) {
            const uint2 pu = __ldg((const uint2*)&g_Ph[(size_t)sI[i] * 128 + 4 * lane]);
            const uint2 qu = __ldg((const uint2*)&g_Qh[(size_t)dI[i] * 128 + 4 * lane]);
            const float2 p01 = __half22float2(*(const __half2*)&pu.x);
            const float2 p23 = __half22float2(*(const __half2*)&pu.y);
            const float2 q01 = __half22float2(*(const __half2*)&qu.x);
            const float2 q23 = __half22float2(*(const __half2*)&qu.y);
            a0[i] = pk2(p01.x + q01.x + b4.x, p01.y + q01.y + b4.y);
            a1[i] = pk2(p23.x + q23.x + b4.z, p23.y + q23.y + b4.w);
        }
    }

#pragma unroll
    for (int kk = 0; kk < 32; kk += 4) {
        const ulonglong2 w0 = *(const ulonglong2*)&swc[(kk + 0) * 128 + 4 * lane];
        const ulonglong2 w1 = *(const ulonglong2*)&swc[(kk + 1) * 128 + 4 * lane];
        const ulonglong2 w2 = *(const ulonglong2*)&swc[(kk + 2) * 128 + 4 * lane];
        const ulonglong2 w3 = *(const ulonglong2*)&swc[(kk + 3) * 128 + 4 * lane];
#pragma unroll
        for (int i = 0; i < EPW; ++i) {
            const float4 ev = *(const float4*)&sefp[i * 32 + kk];  // broadcast
            unsigned long long e2;
            e2 = pk2(ev.x, ev.x); fma2(a0[i], e2, w0.x); fma2(a1[i], e2, w0.y);
            e2 = pk2(ev.y, ev.y); fma2(a0[i], e2, w1.x); fma2(a1[i], e2, w1.y);
            e2 = pk2(ev.z, ev.z); fma2(a0[i], e2, w2.x); fma2(a1[i], e2, w2.y);
            e2 = pk2(ev.w, ev.w); fma2(a0[i], e2, w3.x); fma2(a1[i], e2, w3.y);
        }
    }

    // spill fp16 Y + accumulate fp32 stats
    float4 ls = make_float4(0.f, 0.f, 0.f, 0.f);
    float4 lq = make_float4(0.f, 0.f, 0.f, 0.f);
#pragma unroll
    for (int i = 0; i < EPW; ++i) {
        float x, y, z, w;
        upk2(a0[i], x, y);
        upk2(a1[i], z, w);
        __half2 h01 = __floats2half2_rn(x, y);
        __half2 h23 = __floats2half2_rn(z, w);
        uint2 hv = make_uint2(*(unsigned*)&h01, *(unsigned*)&h23);
        __stcs((uint2*)&g_Yh[(ebase + i) * 128 + 4 * lane], hv);
        ls.x += x; ls.y += y; ls.z += z; ls.w += w;
        lq.x += x * x; lq.y += y * y; lq.z += z * z; lq.w += w * w;
    }
    *(float4*)&sred[warp][4 * lane]  = ls;
    *(float4*)&sred2[warp][4 * lane] = lq;
    __syncthreads();

    const int stripe = (blockIdx.x & (NSTRIPE - 1)) * 128;
    if (tid < 128) {
        float v = 0.f;
#pragma unroll
        for (int w = 0; w < 8; ++w) v += sred[w][tid];
        atomicAdd(&g_sum32[stripe + tid], (double)v);
    } else {
        const int c = tid - 128;
        float v = 0.f;
#pragma unroll
        for (int w = 0; w < 8; ++w) v += sred2[w][c];
        atomicAdd(&g_sumsq32[stripe + c], (double)v);
    }
}

// ---------------- K3: reduce stripes, finalize edge BN -------------------------
__global__ void k3_edge_bn(const float* __restrict__ gint,
                           const float* __restrict__ beint,
                           const float* __restrict__ gupd,
                           const float* __restrict__ beupd) {
    const int c = threadIdx.x;  // 128
    double s = 0.0, sq = 0.0;
#pragma unroll
    for (int j = 0; j < NSTRIPE; ++j) {
        s  += g_sum32[j * 128 + c];
        sq += g_sumsq32[j * 128 + c];
    }
    const double mu  = s / (double)N_EDGES;
    const double var = sq / (double)N_EDGES - mu * mu;
    const float gam = (c < 64) ? gint[c] : gupd[c - 64];
    const float bet = (c < 64) ? beint[c] : beupd[c - 64];
    const float sc = gam * rsqrtf((float)var + EPSBN);
    g_escale[c] = sc;
    g_eshift[c] = bet - (float)mu * sc;
}

// ---------------- KB: stream Yh, BN + act + scatter ----------------------------
__global__ void __launch_bounds__(256)
kB_apply(const int* __restrict__ dst) {
    const int tid = threadIdx.x;
    const int warp = tid >> 5, lane = tid & 31;
    const int s = lane & 15;
    const size_t e = (size_t)blockIdx.x * 16 + (size_t)warp * 2 + (lane >> 4);

    const uint2 gv = __ldcs((const uint2*)&g_Yh[e * 128 + 4 * s]);
    const uint2 uv = __ldcs((const uint2*)&g_Yh[e * 128 + 64 + 4 * s]);

    const float2 g01 = __half22float2(*(const __half2*)&gv.x);
    const float2 g23 = __half22float2(*(const __half2*)&gv.y);
    const float2 u01 = __half22float2(*(const __half2*)&uv.x);
    const float2 u23 = __half22float2(*(const __half2*)&uv.y);

    const float4 gs = *(const float4*)&g_escale[4 * s];
    const float4 gh = *(const float4*)&g_eshift[4 * s];
    const float4 us = *(const float4*)&g_escale[64 + 4 * s];
    const float4 uh = *(const float4*)&g_eshift[64 + 4 * s];

    float4 m;
    m.x = sigf(fmaf(g01.x, gs.x, gh.x)) * spf(fmaf(u01.x, us.x, uh.x));
    m.y = sigf(fmaf(g01.y, gs.y, gh.y)) * spf(fmaf(u01.y, us.y, uh.y));
    m.z = sigf(fmaf(g23.x, gs.z, gh.z)) * spf(fmaf(u23.x, us.z, uh.z));
    m.w = sigf(fmaf(g23.y, gs.w, gh.w)) * spf(fmaf(u23.y, us.w, uh.w));

    const int d = dst[e];
    red_add_v4(&g_agg[(size_t)d * 64 + 4 * s], m);
}

// ---------------- K5: node BN stats over agg (float4 loads) ---------------------
__global__ void __launch_bounds__(256)
k5_node_stats() {
    const int tid = threadIdx.x;
    const int c4 = (tid & 15) * 4;
    const int rsub = tid >> 4;
    const int r0 = blockIdx.x * 512 + rsub;
    const int end = min((blockIdx.x + 1) * 512, N_NODES);

    float4 s = make_float4(0.f, 0.f, 0.f, 0.f);
    float4 q = make_float4(0.f, 0.f, 0.f, 0.f);
    for (int r = r0; r < end; r += 16) {
        const float4 v = *(const float4*)&g_agg[(size_t)r * 64 + c4];
        s.x += v.x; s.y += v.y; s.z += v.z; s.w += v.w;
        q.x += v.x * v.x; q.y += v.y * v.y; q.z += v.z * v.z; q.w += v.w * v.w;
    }
    __shared__ __align__(16) float ss[16][64];
    __shared__ __align__(16) float sq[16][64];
    *(float4*)&ss[rsub][c4] = s;
    *(float4*)&sq[rsub][c4] = q;
    __syncthreads();
    if (tid < 64) {
        float a = 0.f, b = 0.f;
#pragma unroll
        for (int r = 0; r < 16; ++r) { a += ss[r][tid]; b += sq[r][tid]; }
        atomicAdd(&g_nsum[tid], (double)a);
        atomicAdd(&g_nsumsq[tid], (double)b);
    }
}

// ---------------- K6: final output (node BN folded in) --------------------------
__global__ void __launch_bounds__(256)
k6_out(const float* __restrict__ node,
       const float* __restrict__ gbn,
       const float* __restrict__ bebn,
       float* __restrict__ out) {
    __shared__ float snsc[64], snsh[64];
    const int tid = threadIdx.x;
    if (tid < 64) {
        const double mu  = g_nsum[tid]   / (double)N_NODES;
        const double var = g_nsumsq[tid] / (double)N_NODES - mu * mu;
        const float sc = gbn[tid] * rsqrtf((float)var + EPSBN);
        snsc[tid] = sc;
        snsh[tid] = bebn[tid] - (float)mu * sc;
    }
    __syncthreads();

    const size_t i = (size_t)blockIdx.x * 256 + tid;
    if (i >= (size_t)N_NODES * 64) return;
    const int c = (int)(i & 63);
    const float x = node[i] + g_agg[i] * snsc[c] + snsh[c];
    out[i] = fmaxf(x, 0.f) + log1pf(expf(-fabsf(x)));
}

// ---------------- launch ---------------------------------------------------------
extern "C" void kernel_launch(void* const* d_in, const int* in_sizes, int n_in,
                              void* d_out, int out_size) {
    const float* node  = (const float*)d_in[0];
    const float* edge  = (const float*)d_in[1];
    const int*   src   = (const int*)d_in[2];
    const int*   dst   = (const int*)d_in[3];
    const float* Wint  = (const float*)d_in[4];
    const float* bint  = (const float*)d_in[5];
    const float* gint  = (const float*)d_in[6];
    const float* beint = (const float*)d_in[7];
    const float* Wupd  = (const float*)d_in[8];
    const float* bupd  = (const float*)d_in[9];
    const float* gupd  = (const float*)d_in[10];
    const float* beupd = (const float*)d_in[11];
    const float* gbn   = (const float*)d_in[12];
    const float* bebn  = (const float*)d_in[13];
    float* out = (float*)d_out;

    k1_node_gemm<<<N_NODES / (32 * NT), 256>>>(node, Wint, Wupd);
    kA_edge<<<N_EDGES / EPB, 256>>>(edge, src, dst, Wint, Wupd, bint, bupd);
    k3_edge_bn<<<1, 128>>>(gint, beint, gupd, beupd);
    kB_apply<<<N_EDGES / 16, 256>>>(dst);
    k5_node_stats<<<(N_NODES + 511) / 512, 256>>>();
    k6_out<<<((size_t)N_NODES * 64 + 255) / 256, 256>>>(node, gbn, bebn, out);
}